// round 8
// baseline (speedup 1.0000x reference)
#include <cuda_runtime.h>
#include <cstdint>

#define N_NODES 50000
#define E_EDGES 200000
#define R_REL   2
#define D_DIM   256
#define H_HEADS 8
#define DKD     32

// ---------------- scratch (device globals: allocation-free) ----------------
__device__ float g_Wcat[256 * 1280];                         // fused weights
__device__ float g_bcat[1280];                               // fused bias
__device__ float g_C1[(size_t)N_NODES * 1280];               // q|kt0|kt1|vt0|vt1
__device__ float g_esc[(size_t)R_REL * E_EDGES * H_HEADS];   // exp(att)
__device__ float g_den[(size_t)R_REL * N_NODES * H_HEADS];   // softmax denominators
__device__ float g_hacc[(size_t)R_REL * N_NODES * 256];      // aggregated messages

// ---------------------------------------------------------------------------
// Fold rel_att / rel_msg into the K/V projection weights:
//   Wcat[:,   0: 256] = Wq                         bcat = bq
//   Wcat[:, 256: 512] = Wk @ BD(rel_att[0])        bcat = bk @ BD(rel_att[0])
//   Wcat[:, 512: 768] = Wk @ BD(rel_att[1])
//   Wcat[:, 768:1024] = Wv @ BD(rel_msg[0])
//   Wcat[:,1024:1280] = Wv @ BD(rel_msg[1])
// ---------------------------------------------------------------------------
__global__ void fold_weights(const float* __restrict__ Wk, const float* __restrict__ bk,
                             const float* __restrict__ Wq, const float* __restrict__ bq,
                             const float* __restrict__ Wv, const float* __restrict__ bv,
                             const float* __restrict__ rel_att,
                             const float* __restrict__ rel_msg) {
    int j = blockIdx.x;      // output column 0..1279
    int d = threadIdx.x;     // input row 0..255
    float w, b = 0.0f;
    if (j < 256) {
        w = Wq[d * 256 + j];
        b = bq[j];
    } else {
        int seg = (j - 256) >> 8;       // 0,1 -> kt ; 2,3 -> vt
        int jj  = (j - 256) & 255;
        int h = jj >> 5, f = jj & 31;
        int r = seg & 1;
        const float* W  = (seg < 2) ? Wk : Wv;
        const float* bb = (seg < 2) ? bk : bv;
        const float* T  = (seg < 2) ? rel_att : rel_msg;
        const float* Trow = T + ((size_t)(r * H_HEADS + h) * DKD) * DKD + f; // T[r,h,c,f]
        float s = 0.0f, bs = 0.0f;
        #pragma unroll
        for (int c = 0; c < DKD; c++) {
            float t = Trow[(size_t)c * DKD];
            s  += W[d * 256 + h * 32 + c] * t;
            bs += bb[h * 32 + c] * t;
        }
        w = s; b = bs;
    }
    g_Wcat[d * 1280 + j] = w;
    if (d == 0) g_bcat[j] = b;
}

// ---------------------------------------------------------------------------
__global__ void zero_scratch() {
    size_t stride = (size_t)gridDim.x * blockDim.x;
    size_t i0 = (size_t)blockIdx.x * blockDim.x + threadIdx.x;
    const size_t nden = (size_t)R_REL * N_NODES * H_HEADS;
    const size_t nh   = (size_t)R_REL * N_NODES * 256;
    for (size_t i = i0; i < nden; i += stride) g_den[i] = 0.0f;
    for (size_t i = i0; i < nh;   i += stride) g_hacc[i] = 0.0f;
}

// ---------------------------------------------------------------------------
// GEMM1: C1[N,1280] = x[N,256] @ Wcat[256,1280] + bcat
// 128x128 block tile, BK=16, 256 threads, 8x8 per thread (fp32 SIMT).
// ---------------------------------------------------------------------------
__global__ __launch_bounds__(256) void gemm_qkv(const float* __restrict__ x) {
    __shared__ float As[16][128];   // k-major
    __shared__ float Bs[16][128];
    const int tid = threadIdx.x;
    const int m0 = blockIdx.y * 128;
    const int n0 = blockIdx.x * 128;
    const int tx = tid & 15, ty = tid >> 4;

    float acc[8][8];
    #pragma unroll
    for (int i = 0; i < 8; i++)
        #pragma unroll
        for (int j = 0; j < 8; j++) acc[i][j] = 0.0f;

    for (int k0 = 0; k0 < 256; k0 += 16) {
        #pragma unroll
        for (int i = 0; i < 2; i++) {                 // A tile: 128x16
            int lin = tid + i * 256;
            int aRow = lin >> 2;
            int aVec = lin & 3;
            int gm = m0 + aRow;
            float4 v = make_float4(0.f, 0.f, 0.f, 0.f);
            if (gm < N_NODES)
                v = *(const float4*)&x[(size_t)gm * 256 + k0 + aVec * 4];
            As[aVec * 4 + 0][aRow] = v.x;
            As[aVec * 4 + 1][aRow] = v.y;
            As[aVec * 4 + 2][aRow] = v.z;
            As[aVec * 4 + 3][aRow] = v.w;
        }
        #pragma unroll
        for (int i = 0; i < 2; i++) {                 // B tile: 16x128
            int lin = tid + i * 256;
            int bRow = lin >> 5;
            int bc = lin & 31;
            *(float4*)&Bs[bRow][bc * 4] =
                *(const float4*)&g_Wcat[(size_t)(k0 + bRow) * 1280 + n0 + bc * 4];
        }
        __syncthreads();
        #pragma unroll
        for (int k = 0; k < 16; k++) {
            float a[8], b[8];
            *(float4*)&a[0] = *(float4*)&As[k][ty * 8];
            *(float4*)&a[4] = *(float4*)&As[k][ty * 8 + 4];
            *(float4*)&b[0] = *(float4*)&Bs[k][tx * 8];
            *(float4*)&b[4] = *(float4*)&Bs[k][tx * 8 + 4];
            #pragma unroll
            for (int i = 0; i < 8; i++)
                #pragma unroll
                for (int j = 0; j < 8; j++) acc[i][j] += a[i] * b[j];
        }
        __syncthreads();
    }
    #pragma unroll
    for (int i = 0; i < 8; i++) {
        int gm = m0 + ty * 8 + i;
        if (gm >= N_NODES) continue;
        #pragma unroll
        for (int j = 0; j < 8; j += 4) {
            int gn = n0 + tx * 8 + j;
            float4 o;
            o.x = acc[i][j + 0] + g_bcat[gn + 0];
            o.y = acc[i][j + 1] + g_bcat[gn + 1];
            o.z = acc[i][j + 2] + g_bcat[gn + 2];
            o.w = acc[i][j + 3] + g_bcat[gn + 3];
            *(float4*)&g_C1[(size_t)gm * 1280 + gn] = o;
        }
    }
}

// ---------------------------------------------------------------------------
// Edge pass A: one warp per (r,e).  att = <q[dst], kt_r[src]>_head * pri / sqrt(DK)
// Store exp(att); accumulate denominators per (r, dst, head).
// (Max-subtraction elided: att ~ N(0,1), exp is fp32-safe; softmax identical.)
// ---------------------------------------------------------------------------
__global__ __launch_bounds__(256) void edge_att(const int* __restrict__ src,
                                                const int* __restrict__ dst,
                                                const float* __restrict__ rel_pri) {
    int wid = (int)(((size_t)blockIdx.x * blockDim.x + threadIdx.x) >> 5);
    int lane = threadIdx.x & 31;
    if (wid >= R_REL * E_EDGES) return;
    int r = wid / E_EDGES;
    int s = src[wid];
    int dd = dst[wid];
    const float* qrow = g_C1 + (size_t)dd * 1280;
    const float* krow = g_C1 + (size_t)s * 1280 + 256 + (size_t)r * 256;
    float4 q1 = *(const float4*)(qrow + lane * 8);
    float4 q2 = *(const float4*)(qrow + lane * 8 + 4);
    float4 k1 = *(const float4*)(krow + lane * 8);
    float4 k2 = *(const float4*)(krow + lane * 8 + 4);
    float p = q1.x * k1.x + q1.y * k1.y + q1.z * k1.z + q1.w * k1.w
            + q2.x * k2.x + q2.y * k2.y + q2.z * k2.z + q2.w * k2.w;
    p += __shfl_xor_sync(0xffffffffu, p, 1);
    p += __shfl_xor_sync(0xffffffffu, p, 2);
    if ((lane & 3) == 0) {
        int h = lane >> 2;
        float att = p * rel_pri[r * H_HEADS + h] * 0.17677669529663687f; // 1/sqrt(32)
        float ev = __expf(att);
        g_esc[(size_t)wid * 8 + h] = ev;
        atomicAdd(&g_den[((size_t)(r * N_NODES + dd)) * 8 + h], ev);
    }
}

// ---------------------------------------------------------------------------
// Edge pass B: attn = e/den ; hacc[r,dst] += attn_h * vt_r[src]  (v4 reductions)
// ---------------------------------------------------------------------------
__global__ __launch_bounds__(256) void edge_agg(const int* __restrict__ src,
                                                const int* __restrict__ dst) {
    int wid = (int)(((size_t)blockIdx.x * blockDim.x + threadIdx.x) >> 5);
    int lane = threadIdx.x & 31;
    if (wid >= R_REL * E_EDGES) return;
    int r = wid / E_EDGES;
    int s = src[wid];
    int dd = dst[wid];
    int h = lane >> 2;
    float ev = g_esc[(size_t)wid * 8 + h];
    float dn = g_den[((size_t)(r * N_NODES + dd)) * 8 + h];
    float a = ev / dn;
    const float* vrow = g_C1 + (size_t)s * 1280 + 768 + (size_t)r * 256;
    float4 v1 = *(const float4*)(vrow + lane * 8);
    float4 v2 = *(const float4*)(vrow + lane * 8 + 4);
    v1.x *= a; v1.y *= a; v1.z *= a; v1.w *= a;
    v2.x *= a; v2.y *= a; v2.z *= a; v2.w *= a;
    float* op = g_hacc + ((size_t)(r * N_NODES + dd)) * 256 + lane * 8;
    asm volatile("red.global.add.v4.f32 [%0], {%1,%2,%3,%4};"
                 :: "l"(op), "f"(v1.x), "f"(v1.y), "f"(v1.z), "f"(v1.w) : "memory");
    asm volatile("red.global.add.v4.f32 [%0], {%1,%2,%3,%4};"
                 :: "l"(op + 4), "f"(v2.x), "f"(v2.y), "f"(v2.z), "f"(v2.w) : "memory");
}

// ---------------------------------------------------------------------------
// GEMM2: out = ( mean_r(hacc) @ Wa + ba ) * alpha + x * (1 - alpha)
// Fuses relation-mean on the A-tile load and the sigmoid-skip epilogue.
// ---------------------------------------------------------------------------
__global__ __launch_bounds__(256) void gemm_out(const float* __restrict__ Wa,
                                                const float* __restrict__ ba,
                                                const float* __restrict__ x,
                                                const float* __restrict__ skip,
                                                float* __restrict__ out) {
    __shared__ float As[16][128];
    __shared__ float Bs[16][128];
    const int tid = threadIdx.x;
    const int m0 = blockIdx.y * 128;
    const int n0 = blockIdx.x * 128;
    const int tx = tid & 15, ty = tid >> 4;
    const float alpha = 1.0f / (1.0f + __expf(-skip[0]));

    float acc[8][8];
    #pragma unroll
    for (int i = 0; i < 8; i++)
        #pragma unroll
        for (int j = 0; j < 8; j++) acc[i][j] = 0.0f;

    for (int k0 = 0; k0 < 256; k0 += 16) {
        #pragma unroll
        for (int i = 0; i < 2; i++) {
            int lin = tid + i * 256;
            int aRow = lin >> 2;
            int aVec = lin & 3;
            int gm = m0 + aRow;
            float4 v = make_float4(0.f, 0.f, 0.f, 0.f);
            if (gm < N_NODES) {
                float4 u0 = *(const float4*)&g_hacc[(size_t)gm * 256 + k0 + aVec * 4];
                float4 u1 = *(const float4*)&g_hacc[((size_t)N_NODES + gm) * 256 + k0 + aVec * 4];
                v.x = 0.5f * (u0.x + u1.x);
                v.y = 0.5f * (u0.y + u1.y);
                v.z = 0.5f * (u0.z + u1.z);
                v.w = 0.5f * (u0.w + u1.w);
            }
            As[aVec * 4 + 0][aRow] = v.x;
            As[aVec * 4 + 1][aRow] = v.y;
            As[aVec * 4 + 2][aRow] = v.z;
            As[aVec * 4 + 3][aRow] = v.w;
        }
        #pragma unroll
        for (int i = 0; i < 2; i++) {
            int lin = tid + i * 256;
            int bRow = lin >> 5;
            int bc = lin & 31;
            *(float4*)&Bs[bRow][bc * 4] =
                *(const float4*)&Wa[(size_t)(k0 + bRow) * 256 + n0 + bc * 4];
        }
        __syncthreads();
        #pragma unroll
        for (int k = 0; k < 16; k++) {
            float a[8], b[8];
            *(float4*)&a[0] = *(float4*)&As[k][ty * 8];
            *(float4*)&a[4] = *(float4*)&As[k][ty * 8 + 4];
            *(float4*)&b[0] = *(float4*)&Bs[k][tx * 8];
            *(float4*)&b[4] = *(float4*)&Bs[k][tx * 8 + 4];
            #pragma unroll
            for (int i = 0; i < 8; i++)
                #pragma unroll
                for (int j = 0; j < 8; j++) acc[i][j] += a[i] * b[j];
        }
        __syncthreads();
    }
    const float beta = 1.0f - alpha;
    #pragma unroll
    for (int i = 0; i < 8; i++) {
        int gm = m0 + ty * 8 + i;
        if (gm >= N_NODES) continue;
        #pragma unroll
        for (int j = 0; j < 8; j += 4) {
            int gn = n0 + tx * 8 + j;
            float4 xi = *(const float4*)&x[(size_t)gm * 256 + gn];
            float4 o;
            o.x = (acc[i][j + 0] + ba[gn + 0]) * alpha + xi.x * beta;
            o.y = (acc[i][j + 1] + ba[gn + 1]) * alpha + xi.y * beta;
            o.z = (acc[i][j + 2] + ba[gn + 2]) * alpha + xi.z * beta;
            o.w = (acc[i][j + 3] + ba[gn + 3]) * alpha + xi.w * beta;
            *(float4*)&out[(size_t)gm * 256 + gn] = o;
        }
    }
}

// ---------------------------------------------------------------------------
extern "C" void kernel_launch(void* const* d_in, const int* in_sizes, int n_in,
                              void* d_out, int out_size) {
    const float* x       = (const float*)d_in[0];
    const int*   src     = (const int*)d_in[1];
    const int*   dst     = (const int*)d_in[2];
    const float* Wk      = (const float*)d_in[3];
    const float* bk      = (const float*)d_in[4];
    const float* Wq      = (const float*)d_in[5];
    const float* bq      = (const float*)d_in[6];
    const float* Wv      = (const float*)d_in[7];
    const float* bv      = (const float*)d_in[8];
    const float* Wa      = (const float*)d_in[9];
    const float* ba      = (const float*)d_in[10];
    const float* rel_pri = (const float*)d_in[11];
    const float* rel_att = (const float*)d_in[12];
    const float* rel_msg = (const float*)d_in[13];
    const float* skip    = (const float*)d_in[14];
    float* out = (float*)d_out;

    fold_weights<<<1280, 256>>>(Wk, bk, Wq, bq, Wv, bv, rel_att, rel_msg);
    zero_scratch<<<4096, 256>>>();
    gemm_qkv<<<dim3(10, 391), 256>>>(x);

    const int total_warps = R_REL * E_EDGES;          // 400000, 8 warps/block
    edge_att<<<total_warps / 8, 256>>>(src, dst, rel_pri);
    edge_agg<<<total_warps / 8, 256>>>(src, dst);

    gemm_out<<<dim3(2, 391), 256>>>(Wa, ba, x, skip, out);
}

// round 11
// speedup vs baseline: 1.8725x; 1.8725x over previous
#include <cuda_runtime.h>
#include <cuda_bf16.h>
#include <cstdint>

#define N_NODES 50000
#define E_EDGES 200000
#define R_REL   2
#define H_HEADS 8
#define DKD     32

// ---------------- scratch (device globals: allocation-free) ----------------
__device__ float g_bcat[1280];                                         // fused bias
__device__ __align__(16) __nv_bfloat16 g_WTh[1280 * 256];              // Wcat^T hi
__device__ __align__(16) __nv_bfloat16 g_WTl[1280 * 256];              // Wcat^T lo
__device__ __align__(16) __nv_bfloat16 g_WaTh[256 * 256];              // Wa^T hi
__device__ __align__(16) __nv_bfloat16 g_WaTl[256 * 256];              // Wa^T lo
__device__ __align__(16) __nv_bfloat16 g_xh[(size_t)N_NODES * 256];    // x hi
__device__ __align__(16) __nv_bfloat16 g_xl[(size_t)N_NODES * 256];    // x lo
__device__ __align__(16) __nv_bfloat16 g_mh[(size_t)N_NODES * 256];    // mean(hacc) hi
__device__ __align__(16) __nv_bfloat16 g_ml[(size_t)N_NODES * 256];    // mean(hacc) lo
__device__ __align__(16) float g_C1[(size_t)N_NODES * 1280];           // q|kt0|kt1|vt0|vt1
__device__ float g_esc[(size_t)R_REL * E_EDGES * H_HEADS];             // exp(att)
__device__ float g_den[(size_t)R_REL * N_NODES * H_HEADS];             // softmax denominators
__device__ __align__(16) float g_hacc[(size_t)R_REL * N_NODES * 256];  // aggregated messages

// ---------------------------- helpers ---------------------------------------
__device__ __forceinline__ uint32_t smem_u32(const void* p) {
    uint32_t a;
    asm("{ .reg .u64 t; cvta.to.shared.u64 t, %1; cvt.u32.u64 %0, t; }" : "=r"(a) : "l"(p));
    return a;
}
#define SWZ128(off) ((off) ^ (((off) >> 3) & 0x70))

__device__ __forceinline__ void ldm_x4(uint32_t* r, uint32_t addr) {
    asm volatile("ldmatrix.sync.aligned.m8n8.x4.shared.b16 {%0,%1,%2,%3}, [%4];"
                 : "=r"(r[0]), "=r"(r[1]), "=r"(r[2]), "=r"(r[3]) : "r"(addr));
}
__device__ __forceinline__ void mma16816(float* c, const uint32_t* a, const uint32_t* b) {
    asm volatile("mma.sync.aligned.m16n8k16.row.col.f32.bf16.bf16.f32 "
                 "{%0,%1,%2,%3}, {%4,%5,%6,%7}, {%8,%9}, {%0,%1,%2,%3};"
                 : "+f"(c[0]), "+f"(c[1]), "+f"(c[2]), "+f"(c[3])
                 : "r"(a[0]), "r"(a[1]), "r"(a[2]), "r"(a[3]), "r"(b[0]), "r"(b[1]));
}

// ---------------------------------------------------------------------------
// Fold rel_att / rel_msg into the K/V projection weights, emit transposed
// bf16 hi/lo splits for the tensor-core GEMM:
//   Wcat[:,   0: 256] = Wq ; [:,256:768] = Wk@BD(rel_att[r]) ; [:,768:1280] = Wv@BD(rel_msg[r])
// ---------------------------------------------------------------------------
__global__ void fold_weights(const float* __restrict__ Wk, const float* __restrict__ bk,
                             const float* __restrict__ Wq, const float* __restrict__ bq,
                             const float* __restrict__ Wv, const float* __restrict__ bv,
                             const float* __restrict__ rel_att,
                             const float* __restrict__ rel_msg) {
    int j = blockIdx.x;      // output column 0..1279
    int d = threadIdx.x;     // input row 0..255
    float w, b = 0.0f;
    if (j < 256) {
        w = Wq[d * 256 + j];
        b = bq[j];
    } else {
        int seg = (j - 256) >> 8;       // 0,1 -> kt ; 2,3 -> vt
        int jj  = (j - 256) & 255;
        int h = jj >> 5, f = jj & 31;
        int r = seg & 1;
        const float* W  = (seg < 2) ? Wk : Wv;
        const float* bb = (seg < 2) ? bk : bv;
        const float* T  = (seg < 2) ? rel_att : rel_msg;
        const float* Trow = T + ((size_t)(r * H_HEADS + h) * DKD) * DKD + f;
        float s = 0.0f, bs = 0.0f;
        #pragma unroll
        for (int c = 0; c < DKD; c++) {
            float t = Trow[(size_t)c * DKD];
            s  += W[d * 256 + h * 32 + c] * t;
            bs += bb[h * 32 + c] * t;
        }
        w = s; b = bs;
    }
    __nv_bfloat16 hi = __float2bfloat16(w);
    g_WTh[(size_t)j * 256 + d] = hi;
    g_WTl[(size_t)j * 256 + d] = __float2bfloat16(w - __bfloat162float(hi));
    if (d == 0) g_bcat[j] = b;
}

__global__ void cvt_wa(const float* __restrict__ Wa) {
    int j = blockIdx.x;      // output column (n)
    int d = threadIdx.x;     // input row (k)
    float w = Wa[d * 256 + j];
    __nv_bfloat16 hi = __float2bfloat16(w);
    g_WaTh[(size_t)j * 256 + d] = hi;
    g_WaTl[(size_t)j * 256 + d] = __float2bfloat16(w - __bfloat162float(hi));
}

// MODE 0: split x -> g_xh/g_xl.  MODE 1: split 0.5*(hacc0+hacc1) -> g_mh/g_ml.
template<int MODE>
__global__ void cvt_in(const float* __restrict__ x) {
    int i = blockIdx.x * blockDim.x + threadIdx.x;      // float4 index
    if (i >= (N_NODES * 256) / 4) return;
    float4 v;
    if (MODE == 0) {
        v = ((const float4*)x)[i];
    } else {
        float4 a = ((const float4*)g_hacc)[i];
        float4 b = ((const float4*)(g_hacc + (size_t)N_NODES * 256))[i];
        v.x = 0.5f * (a.x + b.x); v.y = 0.5f * (a.y + b.y);
        v.z = 0.5f * (a.z + b.z); v.w = 0.5f * (a.w + b.w);
    }
    __nv_bfloat16* hi = MODE ? g_mh : g_xh;
    __nv_bfloat16* lo = MODE ? g_ml : g_xl;
    __nv_bfloat16 h0 = __float2bfloat16(v.x), h1 = __float2bfloat16(v.y);
    __nv_bfloat16 h2 = __float2bfloat16(v.z), h3 = __float2bfloat16(v.w);
    __nv_bfloat162 H01, H23, L01, L23;
    H01.x = h0; H01.y = h1; H23.x = h2; H23.y = h3;
    L01.x = __float2bfloat16(v.x - __bfloat162float(h0));
    L01.y = __float2bfloat16(v.y - __bfloat162float(h1));
    L23.x = __float2bfloat16(v.z - __bfloat162float(h2));
    L23.y = __float2bfloat16(v.w - __bfloat162float(h3));
    ((__nv_bfloat162*)hi)[2 * i]     = H01;
    ((__nv_bfloat162*)hi)[2 * i + 1] = H23;
    ((__nv_bfloat162*)lo)[2 * i]     = L01;
    ((__nv_bfloat162*)lo)[2 * i + 1] = L23;
}

// ---------------------------------------------------------------------------
__global__ void zero_scratch() {
    size_t stride = (size_t)gridDim.x * blockDim.x;
    size_t i0 = (size_t)blockIdx.x * blockDim.x + threadIdx.x;
    const size_t nden = (size_t)R_REL * N_NODES * H_HEADS;
    const size_t nh   = (size_t)R_REL * N_NODES * 256;
    for (size_t i = i0; i < nden; i += stride) g_den[i] = 0.0f;
    for (size_t i = i0; i < nh;   i += stride) g_hacc[i] = 0.0f;
}

// ---------------------------------------------------------------------------
// mma.sync bf16 GEMM, hi/lo split (3 terms: AhBh + AhBl + AlBh), fp32 accum.
// Block tile 128x128, 8 warps (2x4), warp tile 64x32, BK=64, K=256 (4 chunks).
// SMEM: Ah | Al | Bh | Bl, each 128 rows x 128B (SW128 swizzled) = 16KB -> 64KB.
// MODE 0: C1[N,1280] = x @ Wcat + bcat
// MODE 1: out = (mean(hacc) @ Wa + ba)*alpha + x*(1-alpha)
// ---------------------------------------------------------------------------
#define SMEM_GEMM (4 * 16384)

template<int MODE>
__global__ __launch_bounds__(256, 2)
void gemm_mma(const float* __restrict__ ba, const float* __restrict__ xres,
              const float* __restrict__ skip, float* __restrict__ outp) {
    extern __shared__ char smem[];
    const uint32_t sb = smem_u32(smem);
    const int tid  = threadIdx.x;
    const int lane = tid & 31;
    const int wid  = tid >> 5;
    const int wr   = wid >> 2;          // 0..1  -> m offset wr*64
    const int wc   = wid & 3;           // 0..3  -> n offset wc*32
    const int m0 = blockIdx.y * 128;
    const int n0 = blockIdx.x * 128;
    constexpr int LDC = MODE ? 256 : 1280;

    const __nv_bfloat16* const mats[4] = {
        MODE ? g_mh : g_xh, MODE ? g_ml : g_xl,
        MODE ? g_WaTh : g_WTh, MODE ? g_WaTl : g_WTl };
    const float* bias = MODE ? ba : g_bcat;
    float* C = MODE ? outp : g_C1;

    float acc[4][4][4];                  // [mt][nt][frag]
    #pragma unroll
    for (int i = 0; i < 4; i++)
        #pragma unroll
        for (int j = 0; j < 4; j++)
            #pragma unroll
            for (int t = 0; t < 4; t++) acc[i][j][t] = 0.0f;

    // ldmatrix lane-address components (constant across chunks)
    const int a_row = wr * 64 + (lane & 7) + ((lane >> 3) & 1) * 8;   // + mt*16
    const int a_colb = ((lane >> 4) & 1) * 16;                        // + s*32
    const int b_row = wc * 32 + (lane & 7) + ((lane >> 4) & 1) * 8;   // + j*16
    const int b_colb = ((lane >> 3) & 1) * 16;                        // + s*32

    for (int kc = 0; kc < 4; kc++) {
        const int k0 = kc * 64;
        // ---- fill SMEM tiles (Ah, Al, Bh, Bl) ----
        #pragma unroll
        for (int mi = 0; mi < 4; mi++) {
            const __nv_bfloat16* src = mats[mi];
            const int rbase = (mi < 2) ? m0 : n0;
            const uint32_t sdst = sb + mi * 16384;
            #pragma unroll
            for (int it = 0; it < 4; it++) {
                int slot = tid + it * 256;        // 0..1023
                int row = slot >> 3;              // 0..127
                int seg = slot & 7;               // 16B segment within 128B row
                int grow = rbase + row;
                uint4 v = make_uint4(0u, 0u, 0u, 0u);
                if (mi >= 2 || grow < N_NODES)
                    v = *(const uint4*)(src + (size_t)grow * 256 + k0 + seg * 8);
                uint32_t off = SWZ128((uint32_t)(row * 128 + seg * 16));
                asm volatile("st.shared.v4.b32 [%0], {%1,%2,%3,%4};"
                             :: "r"(sdst + off), "r"(v.x), "r"(v.y), "r"(v.z), "r"(v.w)
                             : "memory");
            }
        }
        __syncthreads();

        // ---- consume: 4 K-steps of 16, 3 hi/lo terms ----
        #pragma unroll
        for (int s = 0; s < 4; s++) {
            uint32_t a[16], bh[8], bl[8];
            const int cb_a = s * 32 + a_colb;
            const int cb_b = s * 32 + b_colb;
            #pragma unroll
            for (int mt = 0; mt < 4; mt++) {     // Ah fragments
                uint32_t off = SWZ128((uint32_t)((a_row + mt * 16) * 128 + cb_a));
                ldm_x4(&a[4 * mt], sb + off);    // tile 0 = Ah
            }
            #pragma unroll
            for (int j = 0; j < 2; j++) {        // Bh fragments (2 n-tiles per x4)
                uint32_t off = SWZ128((uint32_t)((b_row + j * 16) * 128 + cb_b));
                ldm_x4(&bh[4 * j], sb + 2 * 16384 + off);
            }
            #pragma unroll
            for (int j = 0; j < 2; j++) {        // Bl fragments
                uint32_t off = SWZ128((uint32_t)((b_row + j * 16) * 128 + cb_b));
                ldm_x4(&bl[4 * j], sb + 3 * 16384 + off);
            }
            #pragma unroll
            for (int mt = 0; mt < 4; mt++)
                #pragma unroll
                for (int nt = 0; nt < 4; nt++) {
                    mma16816(acc[mt][nt], &a[4 * mt], &bh[2 * nt]);   // Ah*Bh
                    mma16816(acc[mt][nt], &a[4 * mt], &bl[2 * nt]);   // Ah*Bl
                }
            #pragma unroll
            for (int mt = 0; mt < 4; mt++) {     // Al fragments (reuse regs)
                uint32_t off = SWZ128((uint32_t)((a_row + mt * 16) * 128 + cb_a));
                ldm_x4(&a[4 * mt], sb + 16384 + off);
            }
            #pragma unroll
            for (int mt = 0; mt < 4; mt++)
                #pragma unroll
                for (int nt = 0; nt < 4; nt++)
                    mma16816(acc[mt][nt], &a[4 * mt], &bh[2 * nt]);   // Al*Bh
        }
        __syncthreads();   // tiles fully consumed before next overwrite
    }

    // ---- epilogue ----
    float alpha = 0.f, beta = 0.f;
    if (MODE) { alpha = 1.0f / (1.0f + __expf(-skip[0])); beta = 1.0f - alpha; }
    const int crow = m0 + wr * 64 + (lane >> 2);
    const int ccol0 = n0 + wc * 32 + 2 * (lane & 3);
    #pragma unroll
    for (int mt = 0; mt < 4; mt++) {
        #pragma unroll
        for (int half = 0; half < 2; half++) {
            const int gm = crow + mt * 16 + half * 8;
            if (gm >= N_NODES) continue;
            #pragma unroll
            for (int nt = 0; nt < 4; nt++) {
                const int gn = ccol0 + nt * 8;
                float2 o;
                o.x = acc[mt][nt][2 * half + 0] + bias[gn + 0];
                o.y = acc[mt][nt][2 * half + 1] + bias[gn + 1];
                if (MODE) {
                    const float2 xi = *(const float2*)&xres[(size_t)gm * 256 + gn];
                    o.x = o.x * alpha + xi.x * beta;
                    o.y = o.y * alpha + xi.y * beta;
                }
                *(float2*)&C[(size_t)gm * LDC + gn] = o;
            }
        }
    }
}

// ---------------------------------------------------------------------------
// Edge pass A: one warp per (r,e).  att = <q[dst], kt_r[src]>_head * pri / sqrt(DK)
// ---------------------------------------------------------------------------
__global__ __launch_bounds__(256) void edge_att(const int* __restrict__ src,
                                                const int* __restrict__ dst,
                                                const float* __restrict__ rel_pri) {
    int wid = (int)(((size_t)blockIdx.x * blockDim.x + threadIdx.x) >> 5);
    int lane = threadIdx.x & 31;
    if (wid >= R_REL * E_EDGES) return;
    int r = wid / E_EDGES;
    int s = src[wid];
    int dd = dst[wid];
    const float* qrow = g_C1 + (size_t)dd * 1280;
    const float* krow = g_C1 + (size_t)s * 1280 + 256 + (size_t)r * 256;
    float4 q1 = *(const float4*)(qrow + lane * 8);
    float4 q2 = *(const float4*)(qrow + lane * 8 + 4);
    float4 k1 = *(const float4*)(krow + lane * 8);
    float4 k2 = *(const float4*)(krow + lane * 8 + 4);
    float p = q1.x * k1.x + q1.y * k1.y + q1.z * k1.z + q1.w * k1.w
            + q2.x * k2.x + q2.y * k2.y + q2.z * k2.z + q2.w * k2.w;
    p += __shfl_xor_sync(0xffffffffu, p, 1);
    p += __shfl_xor_sync(0xffffffffu, p, 2);
    if ((lane & 3) == 0) {
        int h = lane >> 2;
        float att = p * rel_pri[r * H_HEADS + h] * 0.17677669529663687f; // 1/sqrt(32)
        float ev = __expf(att);
        g_esc[(size_t)wid * 8 + h] = ev;
        atomicAdd(&g_den[((size_t)(r * N_NODES + dd)) * 8 + h], ev);
    }
}

// ---------------------------------------------------------------------------
// Edge pass B: attn = e/den ; hacc[r,dst] += attn_h * vt_r[src]  (v4 reductions)
// ---------------------------------------------------------------------------
__global__ __launch_bounds__(256) void edge_agg(const int* __restrict__ src,
                                                const int* __restrict__ dst) {
    int wid = (int)(((size_t)blockIdx.x * blockDim.x + threadIdx.x) >> 5);
    int lane = threadIdx.x & 31;
    if (wid >= R_REL * E_EDGES) return;
    int r = wid / E_EDGES;
    int s = src[wid];
    int dd = dst[wid];
    int h = lane >> 2;
    float ev = g_esc[(size_t)wid * 8 + h];
    float dn = g_den[((size_t)(r * N_NODES + dd)) * 8 + h];
    float a = ev / dn;
    const float* vrow = g_C1 + (size_t)s * 1280 + 768 + (size_t)r * 256;
    float4 v1 = *(const float4*)(vrow + lane * 8);
    float4 v2 = *(const float4*)(vrow + lane * 8 + 4);
    v1.x *= a; v1.y *= a; v1.z *= a; v1.w *= a;
    v2.x *= a; v2.y *= a; v2.z *= a; v2.w *= a;
    float* op = g_hacc + ((size_t)(r * N_NODES + dd)) * 256 + lane * 8;
    asm volatile("red.global.add.v4.f32 [%0], {%1,%2,%3,%4};"
                 :: "l"(op), "f"(v1.x), "f"(v1.y), "f"(v1.z), "f"(v1.w) : "memory");
    asm volatile("red.global.add.v4.f32 [%0], {%1,%2,%3,%4};"
                 :: "l"(op + 4), "f"(v2.x), "f"(v2.y), "f"(v2.z), "f"(v2.w) : "memory");
}

// ---------------------------------------------------------------------------
extern "C" void kernel_launch(void* const* d_in, const int* in_sizes, int n_in,
                              void* d_out, int out_size) {
    const float* x       = (const float*)d_in[0];
    const int*   src     = (const int*)d_in[1];
    const int*   dst     = (const int*)d_in[2];
    const float* Wk      = (const float*)d_in[3];
    const float* bk      = (const float*)d_in[4];
    const float* Wq      = (const float*)d_in[5];
    const float* bq      = (const float*)d_in[6];
    const float* Wv      = (const float*)d_in[7];
    const float* bv      = (const float*)d_in[8];
    const float* Wa      = (const float*)d_in[9];
    const float* ba      = (const float*)d_in[10];
    const float* rel_pri = (const float*)d_in[11];
    const float* rel_att = (const float*)d_in[12];
    const float* rel_msg = (const float*)d_in[13];
    const float* skip    = (const float*)d_in[14];
    float* out = (float*)d_out;

    cudaFuncSetAttribute(gemm_mma<0>, cudaFuncAttributeMaxDynamicSharedMemorySize, SMEM_GEMM);
    cudaFuncSetAttribute(gemm_mma<1>, cudaFuncAttributeMaxDynamicSharedMemorySize, SMEM_GEMM);

    fold_weights<<<1280, 256>>>(Wk, bk, Wq, bq, Wv, bv, rel_att, rel_msg);
    cvt_wa<<<256, 256>>>(Wa);
    cvt_in<0><<<(N_NODES * 256 / 4 + 255) / 256, 256>>>(x);
    zero_scratch<<<4096, 256>>>();

    gemm_mma<0><<<dim3(10, 391), 256, SMEM_GEMM>>>(nullptr, nullptr, nullptr, nullptr);

    const int total_warps = R_REL * E_EDGES;          // 400000, 8 warps/block
    edge_att<<<total_warps / 8, 256>>>(src, dst, rel_pri);
    edge_agg<<<total_warps / 8, 256>>>(src, dst);

    cvt_in<1><<<(N_NODES * 256 / 4 + 255) / 256, 256>>>(x);
    gemm_mma<1><<<dim3(2, 391), 256, SMEM_GEMM>>>(ba, x, skip, out);
}